// round 2
// baseline (speedup 1.0000x reference)
#include <cuda_runtime.h>

// QKVProjectedLinear: out[n, k*1024+e] = sum_d x[n,d] * Wl[k][e,d]
// where Wl[k] = P_k Ws_k P_k^T, P_k = A_k B_k (rank 64).
// Restructured: M_k = B_k Ws_k^T B_k^T  (64x64),  D_k = A_k M_k^T (1024x64)
//               u = x @ A  (per k),  out_k = u_k @ D_k^T
//
// Shapes: x[16384,1024], W_small[2304,768], A[3,1024,64], B[3,64,768]
// out[16384, 3072] fp32.

typedef unsigned long long u64;

static constexpr int DL = 1024;
static constexpr int DS = 768;
static constexpr int RK = 64;
static constexpr int NKQV = 3;
static constexpr int NTOK = 2 * 8192;           // 16384

// ---- scratch (static device memory; no allocations allowed) ----
__device__ __align__(16) float g_T[NKQV * RK * DS];      // B @ Ws^T   [3,64,768]
__device__ __align__(16) float g_M[NKQV * RK * RK];      // T @ B^T    [3,64,64]
__device__ __align__(16) float g_D[NKQV * DL * RK];      // A @ M^T    [3,1024,64]
__device__ __align__(16) float g_A2T[NKQV * RK * DL];    // A transposed: [(k*64+r), d]
__device__ __align__(16) float g_u[NTOK * NKQV * RK];    // x @ A      [16384, 192]

// ---------------------------------------------------------------------------
// packed f32x2 FMA helpers (sm_100+). ptxas will not auto-fuse these from C++.
// ---------------------------------------------------------------------------
__device__ __forceinline__ void ffma2(u64& d, u64 a, u64 b) {
    asm("fma.rn.f32x2 %0, %1, %2, %0;" : "+l"(d) : "l"(a), "l"(b));
}
__device__ __forceinline__ u64 dup2(float x) {
    u64 r;
    unsigned xi = __float_as_uint(x);
    asm("mov.b64 %0, {%1, %1};" : "=l"(r) : "r"(xi));
    return r;
}

// ---------------------------------------------------------------------------
// zero the split-K accumulation targets
// ---------------------------------------------------------------------------
__global__ void zero_scratch_kernel() {
    int i = blockIdx.x * 256 + threadIdx.x;
    if (i < NKQV * RK * DS) g_T[i] = 0.0f;
    if (i < NKQV * RK * RK) g_M[i] = 0.0f;
}

// ---------------------------------------------------------------------------
// A2T[(k*64+r)*1024 + d] = A[k, d, r]
// ---------------------------------------------------------------------------
__global__ void transposeA_kernel(const float* __restrict__ A) {
    int i = blockIdx.x * 256 + threadIdx.x;
    if (i >= NKQV * RK * DL) return;
    int d  = i & (DL - 1);
    int kr = i >> 10;
    int k  = kr >> 6;
    int r  = kr & 63;
    g_A2T[i] = A[(k << 16) + (d << 6) + r];
}

// ---------------------------------------------------------------------------
// Generic batched GEMM, "NT" dot form:
//   C[m,n] = sum_k A[m,k] * B[n,k]
// BM=BN=128, BK=16, 256 threads, 8x8 register tile with packed f32x2 FMA.
// Optional deterministic-enough split-K via atomicAdd (only used for the tiny
// precompute GEMMs; main GEMMs use kSplit=1 with plain stores).
// K must be a multiple of 16*kSplit. N handled at float4 granularity (N%8==0).
// ---------------------------------------------------------------------------
__global__ __launch_bounds__(256, 2) void gemm_nt_kernel(
    const float* __restrict__ A, int lda, long sAz,
    const float* __restrict__ B, int ldb, long sBz,
    float* __restrict__ C, int ldc, long sCz,
    int M, int N, int K, int kSplit)
{
    __shared__ __align__(16) float As[16][128];
    __shared__ __align__(16) float Bs[16][128];

    int z  = blockIdx.z;
    int kb = z / kSplit;
    int sp = z - kb * kSplit;
    A += (long)kb * sAz;
    B += (long)kb * sBz;
    C += (long)kb * sCz;
    int Klen = K / kSplit;
    int Koff = sp * Klen;

    int m0 = blockIdx.y * 128;
    int n0 = blockIdx.x * 128;
    int tx = threadIdx.x;          // 0..15 -> n
    int ty = threadIdx.y;          // 0..15 -> m
    int tid = ty * 16 + tx;

    u64 acc[8][4];
#pragma unroll
    for (int i = 0; i < 8; i++)
#pragma unroll
        for (int j = 0; j < 4; j++) acc[i][j] = 0ULL;

    for (int k0 = Koff; k0 < Koff + Klen; k0 += 16) {
        // load A tile [128 rows x 16 k], store transposed As[k][m]
#pragma unroll
        for (int i = 0; i < 2; i++) {
            int f4  = tid + i * 256;          // 0..511 float4 slots
            int row = f4 >> 2;
            int c4  = f4 & 3;
            float4 v = make_float4(0.f, 0.f, 0.f, 0.f);
            int gm = m0 + row;
            if (gm < M) v = *(const float4*)(A + (long)gm * lda + k0 + c4 * 4);
            As[c4 * 4 + 0][row] = v.x;
            As[c4 * 4 + 1][row] = v.y;
            As[c4 * 4 + 2][row] = v.z;
            As[c4 * 4 + 3][row] = v.w;
        }
        // load B tile [128 cols x 16 k], store Bs[k][n]
#pragma unroll
        for (int i = 0; i < 2; i++) {
            int f4  = tid + i * 256;
            int row = f4 >> 2;
            int c4  = f4 & 3;
            float4 v = make_float4(0.f, 0.f, 0.f, 0.f);
            int gn = n0 + row;
            if (gn < N) v = *(const float4*)(B + (long)gn * ldb + k0 + c4 * 4);
            Bs[c4 * 4 + 0][row] = v.x;
            Bs[c4 * 4 + 1][row] = v.y;
            Bs[c4 * 4 + 2][row] = v.z;
            Bs[c4 * 4 + 3][row] = v.w;
        }
        __syncthreads();

#pragma unroll
        for (int kk = 0; kk < 16; kk++) {
            float4 a0 = *(const float4*)&As[kk][ty * 8];
            float4 a1 = *(const float4*)&As[kk][ty * 8 + 4];
            // adjacent n-columns pair naturally into f32x2 (lo = n, hi = n+1)
            ulonglong2 b0 = *(const ulonglong2*)&Bs[kk][tx * 8];
            ulonglong2 b1 = *(const ulonglong2*)&Bs[kk][tx * 8 + 4];
            u64 bp[4] = { b0.x, b0.y, b1.x, b1.y };
            float av[8] = { a0.x, a0.y, a0.z, a0.w, a1.x, a1.y, a1.z, a1.w };
#pragma unroll
            for (int i = 0; i < 8; i++) {
                u64 ap = dup2(av[i]);
#pragma unroll
                for (int j = 0; j < 4; j++) ffma2(acc[i][j], ap, bp[j]);
            }
        }
        __syncthreads();
    }

    // store 8x8 tile
    int gnb = n0 + tx * 8;
#pragma unroll
    for (int i = 0; i < 8; i++) {
        int gm = m0 + ty * 8 + i;
        if (gm >= M) continue;
        float* crow = C + (long)gm * ldc;
        const float* av = (const float*)acc[i];   // cols gnb..gnb+7 in order
        if (kSplit > 1) {
#pragma unroll
            for (int j = 0; j < 8; j++) {
                int gn = gnb + j;
                if (gn < N) atomicAdd(&crow[gn], av[j]);
            }
        } else {
            if (gnb < N)     *(float4*)&crow[gnb]     = *(const float4*)&av[0];
            if (gnb + 4 < N) *(float4*)&crow[gnb + 4] = *(const float4*)&av[4];
        }
    }
}

// ---------------------------------------------------------------------------
extern "C" void kernel_launch(void* const* d_in, const int* in_sizes, int n_in,
                              void* d_out, int out_size)
{
    // identify inputs by unique element counts (robust to ordering)
    const float* x  = nullptr;   // 16384*1024      = 16777216
    const float* Wm = nullptr;   // 2304*768        = 1769472
    const float* Ai = nullptr;   // 3*1024*64       = 196608
    const float* Bi = nullptr;   // 3*64*768        = 147456
    for (int i = 0; i < n_in; i++) {
        switch (in_sizes[i]) {
            case 16777216: x  = (const float*)d_in[i]; break;
            case 1769472:  Wm = (const float*)d_in[i]; break;
            case 196608:   Ai = (const float*)d_in[i]; break;
            case 147456:   Bi = (const float*)d_in[i]; break;
            default: break;
        }
    }
    if (!x || !Wm || !Ai || !Bi) return;
    float* out = (float*)d_out;

    float *T, *Mm, *D, *A2T, *u;
    cudaGetSymbolAddress((void**)&T,   g_T);
    cudaGetSymbolAddress((void**)&Mm,  g_M);
    cudaGetSymbolAddress((void**)&D,   g_D);
    cudaGetSymbolAddress((void**)&A2T, g_A2T);
    cudaGetSymbolAddress((void**)&u,   g_u);

    dim3 blk(16, 16);

    // 0) zero split-K accumulation targets (g_T, g_M)
    zero_scratch_kernel<<<(NKQV * RK * DS + 255) / 256, 256>>>();

    // 1) T_k = B_k @ Ws_k^T   : M=64, N=768, K=768, split-K 16
    gemm_nt_kernel<<<dim3(6, 1, NKQV * 16), blk>>>(
        Bi, DS, (long)RK * DS,
        Wm, DS, (long)DS * DS,
        T,  DS, (long)RK * DS,
        RK, DS, DS, 16);

    // 2) M_k = T_k @ B_k^T    : M=64, N=64, K=768, split-K 16
    gemm_nt_kernel<<<dim3(1, 1, NKQV * 16), blk>>>(
        T,  DS, (long)RK * DS,
        Bi, DS, (long)RK * DS,
        Mm, RK, (long)RK * RK,
        RK, RK, DS, 16);

    // 3) D_k = A_k @ M_k^T    : M=1024, N=64, K=64
    gemm_nt_kernel<<<dim3(1, 8, NKQV), blk>>>(
        Ai, RK, (long)DL * RK,
        Mm, RK, (long)RK * RK,
        D,  RK, (long)DL * RK,
        DL, RK, RK, 1);

    // 4) A2T[(k*64+r), d] = A[k, d, r]
    transposeA_kernel<<<(NKQV * RK * DL + 255) / 256, 256>>>(Ai);

    // 5) u = x @ A2T^T        : M=16384, N=192, K=1024
    gemm_nt_kernel<<<dim3(2, 128, 1), blk>>>(
        x,   DL, 0L,
        A2T, DL, 0L,
        u,   NKQV * RK, 0L,
        NTOK, NKQV * RK, DL, 1);

    // 6) out_k = u_k @ D_k^T  : M=16384, N=1024, K=64  (batched over k)
    gemm_nt_kernel<<<dim3(8, 128, NKQV), blk>>>(
        u,   NKQV * RK, (long)RK,
        D,   RK,        (long)DL * RK,
        out, NKQV * DL, (long)DL,
        NTOK, DL, RK, 1);
}

// round 5
// speedup vs baseline: 1.9361x; 1.9361x over previous
#include <cuda_runtime.h>
#include <cuda_bf16.h>

typedef unsigned int u32;
typedef unsigned long long u64;

static constexpr int DL = 1024;
static constexpr int DS = 768;
static constexpr int RK = 64;
static constexpr int NK = 3;
static constexpr int NTOK = 16384;

// ---- static scratch ----
__device__ __align__(16) float g_T[NK * RK * DS];          // B @ Ws^T
__device__ __align__(16) float g_M[NK * RK * RK];          // T @ B^T
__device__ __align__(16) __nv_bfloat16 g_Ah[NK * RK * DL]; // A^T hi  [192][1024]
__device__ __align__(16) __nv_bfloat16 g_Al[NK * RK * DL]; // A^T lo
__device__ __align__(16) __nv_bfloat16 g_Dh[NK * DL * RK]; // D hi    [3][1024][64]
__device__ __align__(16) __nv_bfloat16 g_Dl[NK * DL * RK]; // D lo
__device__ __align__(16) u32 g_uh[NTOK * 96];              // u hi (bf16x2) [16384][96]
__device__ __align__(16) u32 g_ul[NTOK * 96];              // u lo

// =====================================================================
// helpers (baseline PTX only — no 'a'-gated instructions)
// =====================================================================
__device__ __forceinline__ u32 smem_u32(const void* p) {
    u32 a;
    asm("{ .reg .u64 t; cvta.to.shared.u64 t, %1; cvt.u32.u64 %0, t; }" : "=r"(a) : "l"(p));
    return a;
}
__device__ __forceinline__ void cp16(u32 dst, const void* src) {
    asm volatile("cp.async.cg.shared.global [%0], [%1], 16;" :: "r"(dst), "l"(src));
}
__device__ __forceinline__ void cp_commit() { asm volatile("cp.async.commit_group;"); }
__device__ __forceinline__ void cp_wait0()  { asm volatile("cp.async.wait_group 0;"); }

__device__ __forceinline__ void ldsm4(u32 addr, u32 r[4]) {
    asm volatile("ldmatrix.sync.aligned.m8n8.x4.shared.b16 {%0,%1,%2,%3}, [%4];"
                 : "=r"(r[0]), "=r"(r[1]), "=r"(r[2]), "=r"(r[3]) : "r"(addr));
}
__device__ __forceinline__ void mma16816(float c[4], const u32 a[4], const u32 b[2]) {
    asm volatile(
        "mma.sync.aligned.m16n8k16.row.col.f32.bf16.bf16.f32 "
        "{%0,%1,%2,%3}, {%4,%5,%6,%7}, {%8,%9}, {%0,%1,%2,%3};"
        : "+f"(c[0]), "+f"(c[1]), "+f"(c[2]), "+f"(c[3])
        : "r"(a[0]), "r"(a[1]), "r"(a[2]), "r"(a[3]), "r"(b[0]), "r"(b[1]));
}
__device__ __forceinline__ void bsplit2(float v0, float v1, u32& hp, u32& lp) {
    __nv_bfloat16 h0 = __float2bfloat16(v0);
    __nv_bfloat16 h1 = __float2bfloat16(v1);
    __nv_bfloat16 l0 = __float2bfloat16(v0 - __bfloat162float(h0));
    __nv_bfloat16 l1 = __float2bfloat16(v1 - __bfloat162float(h1));
    hp = (u32)__bfloat16_as_ushort(h0) | ((u32)__bfloat16_as_ushort(h1) << 16);
    lp = (u32)__bfloat16_as_ushort(l0) | ((u32)__bfloat16_as_ushort(l1) << 16);
}
// SW128 swizzle for 128-byte rows: (row*128 + b) ^ ((row&7)<<4)
__device__ __forceinline__ u32 swz(u32 row, u32 b) {
    return (row * 128 + b) ^ ((row & 7) << 4);
}

// =====================================================================
// shared mma inner loop: one K=64 chunk.
// Tiles in smem: X (A-operand) [128 rows m][64 k] bf16, 128B rows, SW128.
//                B             [64 rows n][64 k] bf16, 128B rows, SW128.
// Warp (wm 0..3, wn 0..1) computes 32(m) x 32(n); acc[mt][nt][4].
// 3-term split: Xh*Bh + Xh*Bl + Xl*Bh.
// =====================================================================
__device__ __forceinline__ void mma_chunk(
    u32 sXH, u32 sXL, u32 sBH, u32 sBL,
    int wm, int wn, int lane, float acc[2][4][4])
{
    u32 arow  = (u32)(wm * 32) + (lane & 15);
    u32 acolx = ((u32)(lane >> 4)) << 4;
    u32 brow  = (u32)(wn * 32) + (lane & 7) + (((u32)(lane >> 4)) << 3);
    u32 bcolx = (((u32)(lane >> 3)) & 1) << 4;
#pragma unroll
    for (int s = 0; s < 4; s++) {
        u32 sb = (u32)s * 32;
        u32 ah[2][4], al[2][4], bh[2][4], bl[2][4];
#pragma unroll
        for (int mt = 0; mt < 2; mt++) {
            u32 r = arow + (u32)mt * 16;
            u32 off = (r * 128 + sb + acolx) ^ ((r & 7) << 4);
            ldsm4(sXH + off, ah[mt]);
            ldsm4(sXL + off, al[mt]);
        }
#pragma unroll
        for (int ng = 0; ng < 2; ng++) {
            u32 r = brow + (u32)ng * 16;
            u32 off = (r * 128 + sb + bcolx) ^ ((r & 7) << 4);
            ldsm4(sBH + off, bh[ng]);
            ldsm4(sBL + off, bl[ng]);
        }
#pragma unroll
        for (int mt = 0; mt < 2; mt++)
#pragma unroll
            for (int nt = 0; nt < 4; nt++) {
                const u32* bhp = &bh[nt >> 1][(nt & 1) * 2];
                const u32* blp = &bl[nt >> 1][(nt & 1) * 2];
                mma16816(acc[mt][nt], ah[mt], bhp);
                mma16816(acc[mt][nt], ah[mt], blp);
                mma16816(acc[mt][nt], al[mt], bhp);
            }
    }
}

// =====================================================================
// Stage 1: u = x @ A2T^T.  M=16384, N=192 (3 tiles of 64), K=1024.
// CTA 128x64, 256 threads (8 warps, 4m x 2n), K-chunks of 64, double buffer.
// x converted fp32 -> bf16 h/l in-register. Epilogue writes u as bf16 h/l.
// =====================================================================
static constexpr u32 BUFSZ = 49152;  // XH 16K | XL 16K | BH 8K | BL 8K

__global__ __launch_bounds__(256, 2) void gemm_u_kernel(const float* __restrict__ x)
{
    extern __shared__ char smem[];
    u32 sb0 = smem_u32(smem);
    int tid = threadIdx.x, lane = tid & 31, w = tid >> 5;
    int wm = w & 3, wn = w >> 2;
    int n0 = blockIdx.x * 64;
    long row0 = (long)blockIdx.y * 128;

    const char* gAh = (const char*)g_Ah;
    const char* gAl = (const char*)g_Al;

    float4 xr[8];
    float acc[2][4][4];
#pragma unroll
    for (int a = 0; a < 2; a++)
#pragma unroll
        for (int b = 0; b < 4; b++)
#pragma unroll
            for (int c = 0; c < 4; c++) acc[a][b][c] = 0.0f;

    const float4* gxbase = (const float4*)(x + (row0 + (tid >> 1)) * 1024 + (tid & 1) * 32);
    u32 xrow = (u32)(tid >> 1);
    u32 xcb  = (u32)(tid & 1) * 64;

    // prologue: chunk 0
    {
#pragma unroll
        for (int q = 0; q < 8; q++) xr[q] = gxbase[q];
#pragma unroll
        for (int j = 0; j < 2; j++) {
            int idx = tid + 256 * j;
            u32 r = (u32)idx >> 3, c = ((u32)idx & 7) * 16;
            u32 off = swz(r, c);
            long src = (long)(n0 + r) * 2048 + c;
            cp16(sb0 + 32768 + off, gAh + src);
            cp16(sb0 + 40960 + off, gAl + src);
        }
        cp_commit();
#pragma unroll
        for (int q = 0; q < 8; q++) {
            u32 off = swz(xrow, xcb + (u32)q * 8);
            u32 hp0, lp0, hp1, lp1;
            bsplit2(xr[q].x, xr[q].y, hp0, lp0);
            bsplit2(xr[q].z, xr[q].w, hp1, lp1);
            *(u32*)(smem + off)         = hp0;
            *(u32*)(smem + off + 4)     = hp1;
            *(u32*)(smem + 16384 + off) = lp0;
            *(u32*)(smem + 16384 + off + 4) = lp1;
        }
        cp_wait0();
        __syncthreads();
    }

    for (int i = 0; i < 16; i++) {
        int buf = i & 1;
        if (i < 15) {
            int kc = (i + 1) * 64;
#pragma unroll
            for (int q = 0; q < 8; q++) xr[q] = gxbase[kc / 4 + q];
            u32 dstB = sb0 + (u32)(buf ^ 1) * BUFSZ;
#pragma unroll
            for (int j = 0; j < 2; j++) {
                int idx = tid + 256 * j;
                u32 r = (u32)idx >> 3, c = ((u32)idx & 7) * 16;
                u32 off = swz(r, c);
                long src = (long)(n0 + r) * 2048 + (long)kc * 2 + c;
                cp16(dstB + 32768 + off, gAh + src);
                cp16(dstB + 40960 + off, gAl + src);
            }
            cp_commit();
        }
        u32 base = sb0 + (u32)buf * BUFSZ;
        mma_chunk(base, base + 16384, base + 32768, base + 40960, wm, wn, lane, acc);
        if (i < 15) {
            u32 dstX = (u32)(buf ^ 1) * BUFSZ;
#pragma unroll
            for (int q = 0; q < 8; q++) {
                u32 off = dstX + swz(xrow, xcb + (u32)q * 8);
                u32 hp0, lp0, hp1, lp1;
                bsplit2(xr[q].x, xr[q].y, hp0, lp0);
                bsplit2(xr[q].z, xr[q].w, hp1, lp1);
                *(u32*)(smem + off)             = hp0;
                *(u32*)(smem + off + 4)         = hp1;
                *(u32*)(smem + 16384 + off)     = lp0;
                *(u32*)(smem + 16384 + off + 4) = lp1;
            }
        }
        cp_wait0();
        __syncthreads();
    }

    // epilogue: split u to bf16 h/l, write packed u32
#pragma unroll
    for (int mt = 0; mt < 2; mt++)
#pragma unroll
        for (int nt = 0; nt < 4; nt++) {
            long m = row0 + wm * 32 + mt * 16 + (lane >> 2);
            int  n = n0 + wn * 32 + nt * 8 + (lane & 3) * 2;
            u32 hp, lp;
            bsplit2(acc[mt][nt][0], acc[mt][nt][1], hp, lp);
            g_uh[m * 96 + (n >> 1)] = hp;
            g_ul[m * 96 + (n >> 1)] = lp;
            bsplit2(acc[mt][nt][2], acc[mt][nt][3], hp, lp);
            g_uh[(m + 8) * 96 + (n >> 1)] = hp;
            g_ul[(m + 8) * 96 + (n >> 1)] = lp;
        }
}

// =====================================================================
// Stage 2: out_k = u_k @ D_k^T.  M=16384, N=1024 per k (3), K=64.
// CTA 128x64, single-shot smem, direct fp32 stores.
// grid.x = 48 (16 n-tiles x 3 k), grid.y = 128 m-tiles.
// =====================================================================
__global__ __launch_bounds__(256) void gemm_out_kernel(float* __restrict__ out)
{
    extern __shared__ char smem[];
    u32 sb0 = smem_u32(smem);
    int tid = threadIdx.x, lane = tid & 31, w = tid >> 5;
    int wm = w & 3, wn = w >> 2;
    int kb = blockIdx.x >> 4;
    int nw = (blockIdx.x & 15) * 64;
    long row0 = (long)blockIdx.y * 128;

    const char* guh = (const char*)g_uh;   // row stride 384B
    const char* gul = (const char*)g_ul;
    const char* gdh = (const char*)g_Dh;   // row stride 128B
    const char* gdl = (const char*)g_Dl;

    // u tile: 128 rows x 8 chunks x 2 arrays
#pragma unroll
    for (int j = 0; j < 4; j++) {
        int idx = tid + 256 * j;
        u32 r = (u32)idx >> 3, c = ((u32)idx & 7) * 16;
        u32 off = swz(r, c);
        long src = (row0 + r) * 384 + (long)kb * 128 + c;
        cp16(sb0 + off, guh + src);
        cp16(sb0 + 16384 + off, gul + src);
    }
    // D tile: 64 rows x 8 chunks x 2 arrays
#pragma unroll
    for (int j = 0; j < 2; j++) {
        int idx = tid + 256 * j;
        u32 r = (u32)idx >> 3, c = ((u32)idx & 7) * 16;
        u32 off = swz(r, c);
        long src = (long)(kb * 1024 + nw + r) * 128 + c;
        cp16(sb0 + 32768 + off, gdh + src);
        cp16(sb0 + 40960 + off, gdl + src);
    }
    cp_commit();

    float acc[2][4][4];
#pragma unroll
    for (int a = 0; a < 2; a++)
#pragma unroll
        for (int b = 0; b < 4; b++)
#pragma unroll
            for (int c = 0; c < 4; c++) acc[a][b][c] = 0.0f;

    cp_wait0();
    __syncthreads();

    mma_chunk(sb0, sb0 + 16384, sb0 + 32768, sb0 + 40960, wm, wn, lane, acc);

#pragma unroll
    for (int mt = 0; mt < 2; mt++)
#pragma unroll
        for (int nt = 0; nt < 4; nt++) {
            long m = row0 + wm * 32 + mt * 16 + (lane >> 2);
            int col = kb * 1024 + nw + wn * 32 + nt * 8 + (lane & 3) * 2;
            *(float2*)(out + m * 3072 + col) =
                make_float2(acc[mt][nt][0], acc[mt][nt][1]);
            *(float2*)(out + (m + 8) * 3072 + col) =
                make_float2(acc[mt][nt][2], acc[mt][nt][3]);
        }
}

// =====================================================================
// Precompute kernels
// =====================================================================
__device__ __forceinline__ void ffma2(u64& d, u64 a, u64 b) {
    asm("fma.rn.f32x2 %0, %1, %2, %0;" : "+l"(d) : "l"(a), "l"(b));
}
__device__ __forceinline__ u64 dup2(float v) {
    u64 r; unsigned xi = __float_as_uint(v);
    asm("mov.b64 %0, {%1, %1};" : "=l"(r) : "r"(xi));
    return r;
}

__global__ void zero_scratch_kernel() {
    int i = blockIdx.x * 256 + threadIdx.x;
    if (i < NK * RK * DS) g_T[i] = 0.0f;
    if (i < NK * RK * RK) g_M[i] = 0.0f;
}

// A^T + bf16 split: Ah/Al[(k*64+r)*1024 + d] = split(A[k,d,r])
__global__ void transposeA_cvt_kernel(const float* __restrict__ A) {
    int i = blockIdx.x * 256 + threadIdx.x;
    if (i >= NK * RK * DL) return;
    int d = i & (DL - 1);
    int kr = i >> 10;
    int k = kr >> 6;
    int r = kr & 63;
    float v = A[(k << 16) + (d << 6) + r];
    __nv_bfloat16 h = __float2bfloat16(v);
    __nv_bfloat16 l = __float2bfloat16(v - __bfloat162float(h));
    g_Ah[i] = h; g_Al[i] = l;
}

// D_k = A_k @ M_k^T fused with bf16 split. block = 4 d-rows x 64 r.
__global__ void compute_D_kernel(const float* __restrict__ A) {
    __shared__ float Mt[64 * 64];   // Mt[s][r] = M_k[r][s]
    __shared__ float As[4 * 64];
    int k = blockIdx.x;
    int d0 = blockIdx.y * 4;
    int tid = threadIdx.x;
#pragma unroll
    for (int j = 0; j < 16; j++) {
        int i = tid + 256 * j;
        int r = i >> 6, s = i & 63;
        Mt[s * 64 + r] = g_M[k * 4096 + i];
    }
    As[tid] = A[(k << 16) + (d0 + (tid >> 6)) * 64 + (tid & 63)];
    __syncthreads();
    int dl = tid >> 6, r = tid & 63;
    float acc = 0.0f;
#pragma unroll
    for (int s = 0; s < 64; s++) acc += As[dl * 64 + s] * Mt[s * 64 + r];
    __nv_bfloat16 h = __float2bfloat16(acc);
    __nv_bfloat16 l = __float2bfloat16(acc - __bfloat162float(h));
    int o = (k * 1024 + d0 + dl) * 64 + r;
    g_Dh[o] = h; g_Dl[o] = l;
}

// Generic batched NT GEMM (precompute T and M only)
__global__ __launch_bounds__(256, 2) void gemm_nt_kernel(
    const float* __restrict__ A, int lda, long sAz,
    const float* __restrict__ B, int ldb, long sBz,
    float* __restrict__ C, int ldc, long sCz,
    int M, int N, int K, int kSplit)
{
    __shared__ __align__(16) float Ash[16][128];
    __shared__ __align__(16) float Bsh[16][128];

    int z = blockIdx.z;
    int kb = z / kSplit;
    int sp = z - kb * kSplit;
    A += (long)kb * sAz; B += (long)kb * sBz; C += (long)kb * sCz;
    int Klen = K / kSplit;
    int Koff = sp * Klen;

    int m0 = blockIdx.y * 128, n0 = blockIdx.x * 128;
    int tx = threadIdx.x, ty = threadIdx.y;
    int tid = ty * 16 + tx;

    u64 acc[8][4];
#pragma unroll
    for (int i = 0; i < 8; i++)
#pragma unroll
        for (int j = 0; j < 4; j++) acc[i][j] = 0ULL;

    for (int k0 = Koff; k0 < Koff + Klen; k0 += 16) {
#pragma unroll
        for (int i = 0; i < 2; i++) {
            int f4 = tid + i * 256;
            int row = f4 >> 2, c4 = f4 & 3;
            float4 v = make_float4(0.f, 0.f, 0.f, 0.f);
            int gm = m0 + row;
            if (gm < M) v = *(const float4*)(A + (long)gm * lda + k0 + c4 * 4);
            Ash[c4 * 4 + 0][row] = v.x; Ash[c4 * 4 + 1][row] = v.y;
            Ash[c4 * 4 + 2][row] = v.z; Ash[c4 * 4 + 3][row] = v.w;
        }
#pragma unroll
        for (int i = 0; i < 2; i++) {
            int f4 = tid + i * 256;
            int row = f4 >> 2, c4 = f4 & 3;
            float4 v = make_float4(0.f, 0.f, 0.f, 0.f);
            int gn = n0 + row;
            if (gn < N) v = *(const float4*)(B + (long)gn * ldb + k0 + c4 * 4);
            Bsh[c4 * 4 + 0][row] = v.x; Bsh[c4 * 4 + 1][row] = v.y;
            Bsh[c4 * 4 + 2][row] = v.z; Bsh[c4 * 4 + 3][row] = v.w;
        }
        __syncthreads();
#pragma unroll
        for (int kk = 0; kk < 16; kk++) {
            float4 a0 = *(const float4*)&Ash[kk][ty * 8];
            float4 a1 = *(const float4*)&Ash[kk][ty * 8 + 4];
            ulonglong2 b0 = *(const ulonglong2*)&Bsh[kk][tx * 8];
            ulonglong2 b1 = *(const ulonglong2*)&Bsh[kk][tx * 8 + 4];
            u64 bp[4] = { b0.x, b0.y, b1.x, b1.y };
            float av[8] = { a0.x, a0.y, a0.z, a0.w, a1.x, a1.y, a1.z, a1.w };
#pragma unroll
            for (int i = 0; i < 8; i++) {
                u64 ap = dup2(av[i]);
#pragma unroll
                for (int j = 0; j < 4; j++) ffma2(acc[i][j], ap, bp[j]);
            }
        }
        __syncthreads();
    }
    int gnb = n0 + tx * 8;
#pragma unroll
    for (int i = 0; i < 8; i++) {
        int gm = m0 + ty * 8 + i;
        if (gm >= M) continue;
        float* crow = C + (long)gm * ldc;
        const float* av = (const float*)acc[i];
        if (kSplit > 1) {
#pragma unroll
            for (int j = 0; j < 8; j++) {
                int gn = gnb + j;
                if (gn < N) atomicAdd(&crow[gn], av[j]);
            }
        } else {
            if (gnb < N)     *(float4*)&crow[gnb]     = *(const float4*)&av[0];
            if (gnb + 4 < N) *(float4*)&crow[gnb + 4] = *(const float4*)&av[4];
        }
    }
}

// =====================================================================
extern "C" void kernel_launch(void* const* d_in, const int* in_sizes, int n_in,
                              void* d_out, int out_size)
{
    const float* x = nullptr;
    const float* Wm = nullptr;
    const float* Ai = nullptr;
    const float* Bi = nullptr;
    for (int i = 0; i < n_in; i++) {
        switch (in_sizes[i]) {
            case 16777216: x  = (const float*)d_in[i]; break;
            case 1769472:  Wm = (const float*)d_in[i]; break;
            case 196608:   Ai = (const float*)d_in[i]; break;
            case 147456:   Bi = (const float*)d_in[i]; break;
            default: break;
        }
    }
    if (!x || !Wm || !Ai || !Bi) return;
    float* out = (float*)d_out;

    float *T, *Mm;
    cudaGetSymbolAddress((void**)&T,  g_T);
    cudaGetSymbolAddress((void**)&Mm, g_M);

    cudaFuncSetAttribute(gemm_u_kernel,
                         cudaFuncAttributeMaxDynamicSharedMemorySize, 2 * BUFSZ);
    cudaFuncSetAttribute(gemm_out_kernel,
                         cudaFuncAttributeMaxDynamicSharedMemorySize, BUFSZ);

    dim3 blk(16, 16);

    // 0) zero split-K targets
    zero_scratch_kernel<<<(NK * RK * DS + 255) / 256, 256>>>();

    // 1) T_k = B_k @ Ws_k^T : M=64, N=768, K=768, split 16
    gemm_nt_kernel<<<dim3(6, 1, NK * 16), blk>>>(
        Bi, DS, (long)RK * DS, Wm, DS, (long)DS * DS,
        T, DS, (long)RK * DS, RK, DS, DS, 16);

    // 2) M_k = T_k @ B_k^T : M=64, N=64, K=768, split 16
    gemm_nt_kernel<<<dim3(1, 1, NK * 16), blk>>>(
        T, DS, (long)RK * DS, Bi, DS, (long)RK * DS,
        Mm, RK, (long)RK * RK, RK, RK, DS, 16);

    // 3) D_k = A_k @ M_k^T + bf16 split (fused)
    compute_D_kernel<<<dim3(3, 256), 256>>>(Ai);

    // 4) A transpose + bf16 split
    transposeA_cvt_kernel<<<(NK * RK * DL + 255) / 256, 256>>>(Ai);

    // 5) u = x @ A2T^T  (HMMA, 3-term bf16 split)
    gemm_u_kernel<<<dim3(3, 128), 256, 2 * BUFSZ>>>(x);

    // 6) out_k = u_k @ D_k^T  (HMMA)
    gemm_out_kernel<<<dim3(48, 128), 256, BUFSZ>>>(out);
}